// round 5
// baseline (speedup 1.0000x reference)
#include <cuda_runtime.h>

#define KC      64      // number of centers
#define DZN     128     // feature dim
#define OUTD    16      // output dim
#define BM      128     // rows per block
#define NTHREADS 256
#define D2      (DZN/2) // packed f32x2 reduction steps = 64
#define ZPITCH  129     // float2 pitch (rows+1) for zs2  -> conflict-free inner LDS
#define CPITCH  66      // float2 pitch for cs2 (even: keeps 16B alignment options)
#define VPITCH  68      // float pitch for V staging

typedef unsigned long long u64;

__device__ __forceinline__ u64 ffma2(u64 a, u64 b, u64 c) {
    u64 d;
    asm("fma.rn.f32x2 %0, %1, %2, %3;" : "=l"(d) : "l"(a), "l"(b), "l"(c));
    return d;
}
__device__ __forceinline__ float2 u2f(u64 v) {
    float2 r;
    asm("mov.b64 {%0, %1}, %2;" : "=f"(r.x), "=f"(r.y) : "l"(v));
    return r;
}

extern __shared__ char smem_raw[];

__global__ __launch_bounds__(NTHREADS)
void var_net_kernel(const float* __restrict__ z,
                    const float* __restrict__ cnts,
                    const float* __restrict__ lams,
                    const float* __restrict__ W,
                    float* __restrict__ out)
{
    // dynamic smem layout:
    //   zs2: float2 [D2][ZPITCH]  (z tile, transposed, d packed pairwise)
    //   cs2: float2 [D2][CPITCH]  (cnts, transposed, d packed pairwise)
    //   Vs : float  [BM][VPITCH]  (aliases zs2 region after main loop)
    float2* zs2 = (float2*)smem_raw;
    float2* cs2 = (float2*)(smem_raw + (size_t)D2 * ZPITCH * sizeof(float2));
    float*  Vs  = (float*)smem_raw;

    __shared__ float z2s[BM];
    __shared__ float c2s[KC];
    __shared__ float lamss[KC];
    __shared__ float w2s[KC * OUTD];

    const int tid = threadIdx.x;
    const int b0  = blockIdx.x * BM;

    // ---- stage z tile (coalesced global float4, transposed+packed into smem) ----
    const float4* zg = (const float4*)(z + (size_t)b0 * DZN);
    #pragma unroll
    for (int i = tid; i < BM * (DZN / 4); i += NTHREADS) {
        int row = i >> 5;          // 32 float4 per row
        int dg  = i & 31;
        float4 v = zg[(size_t)row * (DZN / 4) + dg];
        zs2[(2 * dg    ) * ZPITCH + row] = make_float2(v.x, v.y);
        zs2[(2 * dg + 1) * ZPITCH + row] = make_float2(v.z, v.w);
    }
    // ---- stage cnts (transposed+packed) ----
    const float4* cg4 = (const float4*)cnts;
    #pragma unroll
    for (int i = tid; i < KC * (DZN / 4); i += NTHREADS) {
        int k  = i >> 5;
        int dg = i & 31;
        float4 v = cg4[k * (DZN / 4) + dg];
        cs2[(2 * dg    ) * CPITCH + k] = make_float2(v.x, v.y);
        cs2[(2 * dg + 1) * CPITCH + k] = make_float2(v.z, v.w);
    }
    // ---- W^2 and lams ----
    #pragma unroll
    for (int i = tid; i < KC * OUTD; i += NTHREADS) { float w = W[i]; w2s[i] = w * w; }
    if (tid < KC) lamss[tid] = lams[tid];
    __syncthreads();

    // ---- per-row ||z||^2 and per-center ||c||^2 from smem ----
    if (tid < BM) {
        float s = 0.f;
        #pragma unroll 16
        for (int d2 = 0; d2 < D2; ++d2) {
            float2 v = zs2[d2 * ZPITCH + tid];
            s += v.x * v.x + v.y * v.y;
        }
        z2s[tid] = s;
    } else if (tid < BM + KC) {
        int k = tid - BM;
        float s = 0.f;
        #pragma unroll 16
        for (int d2 = 0; d2 < D2; ++d2) {
            float2 v = cs2[d2 * CPITCH + k];
            s += v.x * v.x + v.y * v.y;
        }
        c2s[k] = s;
    }
    __syncthreads();

    // ---- main GEMM: 8 rows x 4 cols per thread, f32x2-packed reduction ----
    const int rg = tid & 15;   // rows: rg + 16*i
    const int cg = tid >> 4;   // cols: cg*4 + j
    u64 acc[8][4];
    #pragma unroll
    for (int i = 0; i < 8; i++)
        #pragma unroll
        for (int j = 0; j < 4; j++) acc[i][j] = 0ull;

    #pragma unroll 8
    for (int d2 = 0; d2 < D2; ++d2) {
        u64 zf[8], cf[4];
        const u64* zp = (const u64*)(zs2 + d2 * ZPITCH + rg);
        #pragma unroll
        for (int i = 0; i < 8; i++) zf[i] = zp[16 * i];
        const u64* cp = (const u64*)(cs2 + d2 * CPITCH + cg * 4);
        #pragma unroll
        for (int j = 0; j < 4; j++) cf[j] = cp[j];
        #pragma unroll
        for (int i = 0; i < 8; i++)
            #pragma unroll
            for (int j = 0; j < 4; j++)
                acc[i][j] = ffma2(zf[i], cf[j], acc[i][j]);
    }

    // ---- epilogue part 1: t1 -> V = exp(-lam*t1) in registers ----
    float Vloc[8][4];
    #pragma unroll
    for (int i = 0; i < 8; i++) {
        int r = rg + 16 * i;
        float z2v = z2s[r];
        #pragma unroll
        for (int j = 0; j < 4; j++) {
            int k = cg * 4 + j;
            float2 p  = u2f(acc[i][j]);
            float dot = p.x + p.y;
            float t1  = z2v + c2s[k] - 2.f * dot;
            Vloc[i][j] = __expf(-lamss[k] * t1);   // underflows to 0 like fp32 ref
        }
    }

    __syncthreads();  // everyone done reading zs2 before aliasing as Vs
    #pragma unroll
    for (int i = 0; i < 8; i++) {
        int r = rg + 16 * i;
        #pragma unroll
        for (int j = 0; j < 4; j++)
            Vs[r * VPITCH + cg * 4 + j] = Vloc[i][j];
    }
    __syncthreads();

    // ---- epilogue part 2: beta = V @ W^2 + eps ; sigma = rsqrt(beta) ----
    {
        int r  = tid >> 1;
        int ob = (tid & 1) * 8;
        float accO[8];
        #pragma unroll
        for (int j = 0; j < 8; j++) accO[j] = 0.f;

        #pragma unroll 8
        for (int k = 0; k < KC; k++) {
            float v = Vs[r * VPITCH + k];
            const float4* wv = (const float4*)(w2s + k * OUTD + ob);
            float4 w0 = wv[0], w1 = wv[1];
            accO[0] += v * w0.x; accO[1] += v * w0.y;
            accO[2] += v * w0.z; accO[3] += v * w0.w;
            accO[4] += v * w1.x; accO[5] += v * w1.y;
            accO[6] += v * w1.z; accO[7] += v * w1.w;
        }

        float4 o0, o1;
        o0.x = rsqrtf(accO[0] + 1e-6f);
        o0.y = rsqrtf(accO[1] + 1e-6f);
        o0.z = rsqrtf(accO[2] + 1e-6f);
        o0.w = rsqrtf(accO[3] + 1e-6f);
        o1.x = rsqrtf(accO[4] + 1e-6f);
        o1.y = rsqrtf(accO[5] + 1e-6f);
        o1.z = rsqrtf(accO[6] + 1e-6f);
        o1.w = rsqrtf(accO[7] + 1e-6f);

        float4* og = (float4*)(out + (size_t)(b0 + r) * OUTD + ob);
        og[0] = o0;
        og[1] = o1;
    }
}

extern "C" void kernel_launch(void* const* d_in, const int* in_sizes, int n_in,
                              void* d_out, int out_size)
{
    const float* z    = (const float*)d_in[0];
    const float* cnts = (const float*)d_in[1];
    const float* lams = (const float*)d_in[2];
    const float* W    = (const float*)d_in[3];
    float* out        = (float*)d_out;

    int Btot = in_sizes[0] / DZN;
    size_t smem = (size_t)D2 * ZPITCH * sizeof(float2)
                + (size_t)D2 * CPITCH * sizeof(float2);

    cudaFuncSetAttribute(var_net_kernel,
                         cudaFuncAttributeMaxDynamicSharedMemorySize, (int)smem);
    var_net_kernel<<<Btot / BM, NTHREADS, smem>>>(z, cnts, lams, W, out);
}

// round 7
// speedup vs baseline: 1.0556x; 1.0556x over previous
#include <cuda_runtime.h>

#define KC      64      // centers
#define DZN     128     // feature dim
#define OUTD    16      // output dim
#define BM      128     // rows per block
#define NTHREADS 128
#define D2      (DZN/2) // packed f32x2 reduction steps = 64
#define ZPITCH  129     // float2 pitch for zs2
#define CPITCH  66      // float2 pitch for cs2 (even -> 16B-aligned LDS.128)
#define VPITCH  130     // float pitch for transposed V staging Vs[k][r]

typedef unsigned long long u64;

__device__ __forceinline__ u64 ffma2(u64 a, u64 b, u64 c) {
    u64 d;
    asm("fma.rn.f32x2 %0, %1, %2, %3;" : "=l"(d) : "l"(a), "l"(b), "l"(c));
    return d;
}
__device__ __forceinline__ float2 u2f(u64 v) {
    float2 r;
    asm("mov.b64 {%0, %1}, %2;" : "=f"(r.x), "=f"(r.y) : "l"(v));
    return r;
}
__device__ __forceinline__ u64 pack2(float x, float y) {
    u64 r;
    asm("mov.b64 %0, {%1, %2};" : "=l"(r) : "f"(x), "f"(y));
    return r;
}

extern __shared__ char smem_raw[];

__global__ __launch_bounds__(NTHREADS)
void var_net_kernel(const float* __restrict__ z,
                    const float* __restrict__ cnts,
                    const float* __restrict__ lams,
                    const float* __restrict__ W,
                    float* __restrict__ out)
{
    // dynamic smem:
    //   zs2: float2 [D2][ZPITCH]   (66,048 B)  -- aliased by Vs after main loop
    //   cs2: float2 [D2][CPITCH]   (33,792 B)
    //   Vs : float  [KC][VPITCH]   (33,280 B, transposed: Vs[k*VPITCH + row])
    float2* zs2 = (float2*)smem_raw;
    float2* cs2 = (float2*)(smem_raw + (size_t)D2 * ZPITCH * sizeof(float2));
    float*  Vs  = (float*)smem_raw;

    __shared__ float z2s[BM];
    __shared__ float c2s[KC];
    __shared__ float lamss[KC];
    __shared__ __align__(16) float w2s[KC * OUTD];

    const int tid = threadIdx.x;
    const int b0  = blockIdx.x * BM;

    // ---- stage z tile (coalesced float4, transposed+packed) ----
    const float4* zg = (const float4*)(z + (size_t)b0 * DZN);
    #pragma unroll
    for (int i = tid; i < BM * (DZN / 4); i += NTHREADS) {
        int row = i >> 5;          // 32 float4 per row
        int dg  = i & 31;
        float4 v = zg[(size_t)row * (DZN / 4) + dg];
        zs2[(2 * dg    ) * ZPITCH + row] = make_float2(v.x, v.y);
        zs2[(2 * dg + 1) * ZPITCH + row] = make_float2(v.z, v.w);
    }
    // ---- stage cnts (transposed+packed) ----
    const float4* cg4 = (const float4*)cnts;
    #pragma unroll
    for (int i = tid; i < KC * (DZN / 4); i += NTHREADS) {
        int k  = i >> 5;
        int dg = i & 31;
        float4 v = cg4[k * (DZN / 4) + dg];
        cs2[(2 * dg    ) * CPITCH + k] = make_float2(v.x, v.y);
        cs2[(2 * dg + 1) * CPITCH + k] = make_float2(v.z, v.w);
    }
    // ---- W^2 and lams ----
    #pragma unroll
    for (int i = tid; i < KC * OUTD; i += NTHREADS) { float w = W[i]; w2s[i] = w * w; }
    if (tid < KC) lamss[tid] = lams[tid];
    __syncthreads();

    // ---- ||z||^2 per row (all threads) and ||c||^2 per center (first 64) ----
    {
        float s = 0.f;
        #pragma unroll 16
        for (int d2 = 0; d2 < D2; ++d2) {
            float2 v = zs2[d2 * ZPITCH + tid];
            s += v.x * v.x + v.y * v.y;
        }
        z2s[tid] = s;
    }
    if (tid < KC) {
        float s = 0.f;
        #pragma unroll 16
        for (int d2 = 0; d2 < D2; ++d2) {
            float2 v = cs2[d2 * CPITCH + tid];
            s += v.x * v.x + v.y * v.y;
        }
        c2s[tid] = s;
    }
    __syncthreads();

    // ---- main GEMM: 8 rows x 8 cols per thread, f32x2-packed reduction ----
    const int rg = tid & 15;   // rows: rg + 16*i  (i = 0..7)
    const int cg = tid >> 4;   // cols: cg*8 + j   (cg = 0..7, j = 0..7)
    u64 acc[8][8];
    #pragma unroll
    for (int i = 0; i < 8; i++)
        #pragma unroll
        for (int j = 0; j < 8; j++) acc[i][j] = 0ull;

    #pragma unroll 4
    for (int d2 = 0; d2 < D2; ++d2) {
        u64 zf[8], cf[8];
        const u64* zp = (const u64*)(zs2 + d2 * ZPITCH + rg);
        #pragma unroll
        for (int i = 0; i < 8; i++) zf[i] = zp[16 * i];
        const ulonglong2* cp = (const ulonglong2*)(cs2 + d2 * CPITCH + cg * 8);
        #pragma unroll
        for (int j2 = 0; j2 < 4; j2++) {
            ulonglong2 t = cp[j2];
            cf[2 * j2]     = t.x;
            cf[2 * j2 + 1] = t.y;
        }
        #pragma unroll
        for (int i = 0; i < 8; i++)
            #pragma unroll
            for (int j = 0; j < 8; j++)
                acc[i][j] = ffma2(zf[i], cf[j], acc[i][j]);
    }

    // ---- epilogue part 1: t1 -> V = exp(-lam*t1) ----
    float Vloc[8][8];
    #pragma unroll
    for (int i = 0; i < 8; i++) {
        int r = rg + 16 * i;
        float z2v = z2s[r];
        #pragma unroll
        for (int j = 0; j < 8; j++) {
            int k = cg * 8 + j;
            float2 p  = u2f(acc[i][j]);
            float dot = p.x + p.y;
            float t1  = z2v + c2s[k] - 2.f * dot;
            Vloc[i][j] = __expf(-lamss[k] * t1);
        }
    }

    __syncthreads();  // all reads of zs2 done before aliasing as Vs
    #pragma unroll
    for (int i = 0; i < 8; i++) {
        int r = rg + 16 * i;
        #pragma unroll
        for (int j = 0; j < 8; j++) {
            int k = cg * 8 + j;
            Vs[k * VPITCH + r] = Vloc[i][j];   // transposed, conflict-free
        }
    }
    __syncthreads();

    // ---- epilogue part 2: beta = V @ W^2 + eps ; sigma = rsqrt(beta) ----
    {
        const int r = tid;           // one output row per thread
        u64 accO[8];
        #pragma unroll
        for (int m = 0; m < 8; m++) accO[m] = 0ull;

        #pragma unroll 8
        for (int k = 0; k < KC; k++) {
            float v  = Vs[k * VPITCH + r];
            u64  v2  = pack2(v, v);
            const ulonglong2* wp = (const ulonglong2*)w2s + k * 4; // 16 floats/row
            #pragma unroll
            for (int m = 0; m < 4; m++) {
                ulonglong2 t = wp[m];
                accO[2 * m]     = ffma2(v2, t.x, accO[2 * m]);
                accO[2 * m + 1] = ffma2(v2, t.y, accO[2 * m + 1]);
            }
        }

        float4 o[4];
        #pragma unroll
        for (int m = 0; m < 4; m++) {
            float2 a = u2f(accO[2 * m]);
            float2 b = u2f(accO[2 * m + 1]);
            o[m].x = rsqrtf(a.x + 1e-6f);
            o[m].y = rsqrtf(a.y + 1e-6f);
            o[m].z = rsqrtf(b.x + 1e-6f);
            o[m].w = rsqrtf(b.y + 1e-6f);
        }
        float4* og = (float4*)(out + (size_t)(b0 + r) * OUTD);
        og[0] = o[0]; og[1] = o[1]; og[2] = o[2]; og[3] = o[3];
    }
}

extern "C" void kernel_launch(void* const* d_in, const int* in_sizes, int n_in,
                              void* d_out, int out_size)
{
    const float* z    = (const float*)d_in[0];
    const float* cnts = (const float*)d_in[1];
    const float* lams = (const float*)d_in[2];
    const float* W    = (const float*)d_in[3];
    float* out        = (float*)d_out;

    int Btot = in_sizes[0] / DZN;
    size_t smem = (size_t)D2 * ZPITCH * sizeof(float2)
                + (size_t)D2 * CPITCH * sizeof(float2);

    cudaFuncSetAttribute(var_net_kernel,
                         cudaFuncAttributeMaxDynamicSharedMemorySize, (int)smem);
    var_net_kernel<<<Btot / BM, NTHREADS, smem>>>(z, cnts, lams, W, out);
}